// round 9
// baseline (speedup 1.0000x reference)
#include <cuda_runtime.h>
#include <cuda_bf16.h>
#include <cfloat>
#include <cstdint>

#define NPTS 1024
#define BATCH 8
#define DIN 60
#define DPAD 64
#define KNN 20
#define P1 (BATCH*NPTS*KNN)   /* 163840 */
#define P2 (BATCH*NPTS)       /* 8192 */
#define BN_EPS 1e-5f
#define SLOPE 0.2f

// ---------------- scratch ----------------
__device__ float g_xt[BATCH*NPTS*DPAD];
__device__ float g_xx[BATCH*NPTS];
__device__ int   g_idx[BATCH*NPTS*KNN];
__device__ float g_w1p[64*128];
__device__ float g_h1[P1*64];
__device__ float g_h2[P1*64];
__device__ float g_h3[P1*128];
__device__ float g_h4[P1*256];
__device__ float g_xc[P2*512];
__device__ float g_h5[P2*256];
__device__ float g_h6[P2*1024];
__device__ float g_psum[640*1024];
__device__ float g_psq[640*1024];
__device__ float g_scl[6*1024];
__device__ float g_sft[6*1024];

// ---------------- transpose + squared norm ----------------
__global__ void k_transpose(const float* __restrict__ x) {
    int b = blockIdx.x;
    int n = blockIdx.y * 256 + threadIdx.x;
    float ss = 0.f;
    int obase = (b*NPTS + n)*DPAD;
    #pragma unroll 4
    for (int d = 0; d < DIN; d++) {
        float v = x[(b*DIN + d)*NPTS + n];
        g_xt[obase + d] = v;
        ss += v*v;
    }
    #pragma unroll
    for (int d = DIN; d < DPAD; d++) g_xt[obase + d] = 0.f;
    g_xx[b*NPTS + n] = ss;
}

// ---------------- knn (validated round 2) ----------------
extern __shared__ float s_knn[];
__global__ __launch_bounds__(256) void k_knn() {
    int bb = blockIdx.y;
    int q0 = blockIdx.x * 16;
    float* qs  = s_knn;
    float* xxq = s_knn + 1024;
    float* pd  = s_knn + 1040;
    float* cs  = s_knn + 1040 + 16384;
    int tid = threadIdx.x;
    {
        const float4* src = (const float4*)(g_xt + (bb*NPTS + q0)*DPAD);
        ((float4*)qs)[tid] = src[tid];
    }
    if (tid < 16) xxq[tid] = g_xx[bb*NPTS + q0 + tid];
    __syncthreads();
    int qi0 = (tid >> 5) << 1;
    int mi0 = (tid & 31) << 1;
    for (int t = 0; t < NPTS/64; t++) {
        int m0 = t*64;
        {
            const float4* src = (const float4*)(g_xt + (bb*NPTS + m0)*DPAD);
            #pragma unroll
            for (int j = 0; j < 4; j++) {
                int i = tid + 256*j;
                int row = i >> 4, col = i & 15;
                float4 v = src[row*16 + col];
                float* dr = cs + row*68 + col*4;
                dr[0]=v.x; dr[1]=v.y; dr[2]=v.z; dr[3]=v.w;
            }
        }
        __syncthreads();
        float a00=0,a01=0,a10=0,a11=0;
        #pragma unroll
        for (int d4 = 0; d4 < 16; d4++) {
            float4 qa = *(const float4*)(qs + qi0*64 + d4*4);
            float4 qb = *(const float4*)(qs + (qi0+1)*64 + d4*4);
            float4 ca = *(const float4*)(cs + mi0*68 + d4*4);
            float4 cb = *(const float4*)(cs + (mi0+1)*68 + d4*4);
            a00 += qa.x*ca.x + qa.y*ca.y + qa.z*ca.z + qa.w*ca.w;
            a01 += qa.x*cb.x + qa.y*cb.y + qa.z*cb.z + qa.w*cb.w;
            a10 += qb.x*ca.x + qb.y*ca.y + qb.z*ca.z + qb.w*ca.w;
            a11 += qb.x*cb.x + qb.y*cb.y + qb.z*cb.z + qb.w*cb.w;
        }
        float xc0 = g_xx[bb*NPTS + m0 + mi0];
        float xc1 = g_xx[bb*NPTS + m0 + mi0 + 1];
        pd[(qi0  )*NPTS + m0 + mi0    ] = 2.f*a00 - xxq[qi0  ] - xc0;
        pd[(qi0  )*NPTS + m0 + mi0 + 1] = 2.f*a01 - xxq[qi0  ] - xc1;
        pd[(qi0+1)*NPTS + m0 + mi0    ] = 2.f*a10 - xxq[qi0+1] - xc0;
        pd[(qi0+1)*NPTS + m0 + mi0 + 1] = 2.f*a11 - xxq[qi0+1] - xc1;
        __syncthreads();
    }
    int w = tid >> 5, lane = tid & 31;
    for (int t = 0; t < 2; t++) {
        int qi = w*2 + t;
        float* row = pd + qi*NPTS;
        for (int it = 0; it < KNN; it++) {
            float best = -FLT_MAX; int bi = NPTS;
            for (int m = lane; m < NPTS; m += 32) {
                float v = row[m];
                if (v > best) { best = v; bi = m; }
            }
            #pragma unroll
            for (int off = 16; off; off >>= 1) {
                float ov = __shfl_down_sync(0xffffffffu, best, off);
                int   oi = __shfl_down_sync(0xffffffffu, bi,   off);
                if (ov > best || (ov == best && oi < bi)) { best = ov; bi = oi; }
            }
            bi = __shfl_sync(0xffffffffu, bi, 0);
            if (lane == 0) {
                g_idx[(bb*NPTS + q0 + qi)*KNN + it] = bi;
                row[bi] = -FLT_MAX;
            }
            __syncwarp();
        }
    }
}

__global__ void k_padw1(const float* __restrict__ w1) {
    int o = blockIdx.x, c = threadIdx.x;
    g_w1p[o*128 + c] = (c < 120) ? w1[o*120 + c] : 0.f;
}

// ---------------- bf16 split helper ----------------
__device__ __forceinline__ void split4(float4 v, uint2& hh, uint2& ll) {
    __nv_bfloat162 ph0 = __floats2bfloat162_rn(v.x, v.y);
    __nv_bfloat162 ph1 = __floats2bfloat162_rn(v.z, v.w);
    __nv_bfloat162 pl0 = __floats2bfloat162_rn(v.x - __low2float(ph0), v.y - __high2float(ph0));
    __nv_bfloat162 pl1 = __floats2bfloat162_rn(v.z - __low2float(ph1), v.w - __high2float(ph1));
    hh.x = *reinterpret_cast<uint32_t*>(&ph0); hh.y = *reinterpret_cast<uint32_t*>(&ph1);
    ll.x = *reinterpret_cast<uint32_t*>(&pl0); ll.y = *reinterpret_cast<uint32_t*>(&pl1);
}

__device__ __forceinline__ void mma16816(float* d, const uint32_t* a, uint32_t b0, uint32_t b1) {
    asm volatile("mma.sync.aligned.m16n8k16.row.col.f32.bf16.bf16.f32 "
                 "{%0,%1,%2,%3}, {%4,%5,%6,%7}, {%8,%9}, {%0,%1,%2,%3};"
                 : "+f"(d[0]), "+f"(d[1]), "+f"(d[2]), "+f"(d[3])
                 : "r"(a[0]), "r"(a[1]), "r"(a[2]), "r"(a[3]), "r"(b0), "r"(b1));
}

// ---------------- mma.sync bf16-split GEMM ----------------
// C[M, n0..n0+NT] = A[M,K] * W[N,K]^T + bias, fp32 accum.
// MODE 0: plain A. MODE 1: A = lrelu(A*scl+sft). MODE 2: graph-feature gather.
template<int NT, int KTOT, int MODE>
__global__ __launch_bounds__(256)
void k_gemm_mma(const float* __restrict__ Ain, const float* __restrict__ Wm,
                const float* __restrict__ bias, const float* __restrict__ scl,
                const float* __restrict__ sft, float* __restrict__ C, int Nfull)
{
    constexpr int WN = NT/32;          // warps along n (2 or 4)
    constexpr int WM = 8/WN;           // warps along m (4 or 2)
    constexpr int TM = 128/(WM*16);    // m16 blocks per warp (2 or 4)
    constexpr int STR = 20;            // uint32 words per smem row (80B)
    __shared__ uint32_t As[2][128*STR];
    __shared__ uint32_t Bs[2][NT*STR];

    int tid = threadIdx.x;
    int warp = tid >> 5, lane = tid & 31;
    int wm = warp % WM, wn = warp / WM;
    int m0 = blockIdx.x * 128;
    int n0 = blockIdx.y * NT;
    int lr = lane >> 2, lc = lane & 3;

    float acc[TM][4][4];
    #pragma unroll
    for (int i = 0; i < TM; i++)
        #pragma unroll
        for (int j = 0; j < 4; j++)
            #pragma unroll
            for (int q = 0; q < 4; q++) acc[i][j][q] = 0.f;

    for (int k0 = 0; k0 < KTOT; k0 += 32) {
        // ---- load A tile: 128 rows x 32 k ----
        #pragma unroll
        for (int j = 0; j < 4; j++) {
            int idx = tid + 256*j;
            int r = idx >> 3, c4 = idx & 7;
            int kk = k0 + c4*4;
            float4 v;
            if (MODE == 2) {
                int p = m0 + r;
                int bn = p / KNN;
                int b = bn >> 10;
                int nb = g_idx[p];
                int cbase = bn * DPAD;
                int nbase = ((b << 10) + nb) * DPAD;
                float e[4];
                #pragma unroll
                for (int t = 0; t < 4; t++) {
                    int k = kk + t;
                    float val;
                    if (k < 60)       val = g_xt[nbase + k] - g_xt[cbase + k];
                    else if (k < 120) val = g_xt[cbase + k - 60];
                    else              val = 0.f;
                    e[t] = val;
                }
                v.x = e[0]; v.y = e[1]; v.z = e[2]; v.w = e[3];
            } else {
                v = *(const float4*)(Ain + (size_t)(m0 + r)*KTOT + kk);
                if (MODE == 1) {
                    float4 s4 = *(const float4*)(scl + kk);
                    float4 t4 = *(const float4*)(sft + kk);
                    v.x = fmaf(v.x, s4.x, t4.x); v.y = fmaf(v.y, s4.y, t4.y);
                    v.z = fmaf(v.z, s4.z, t4.z); v.w = fmaf(v.w, s4.w, t4.w);
                    v.x = (v.x >= 0.f) ? v.x : SLOPE*v.x;
                    v.y = (v.y >= 0.f) ? v.y : SLOPE*v.y;
                    v.z = (v.z >= 0.f) ? v.z : SLOPE*v.z;
                    v.w = (v.w >= 0.f) ? v.w : SLOPE*v.w;
                }
            }
            uint2 hh, ll; split4(v, hh, ll);
            *reinterpret_cast<uint2*>(&As[0][r*STR + c4*2]) = hh;
            *reinterpret_cast<uint2*>(&As[1][r*STR + c4*2]) = ll;
        }
        // ---- load B tile: NT rows x 32 k ----
        #pragma unroll
        for (int j = 0; j < NT/32; j++) {
            int idx = tid + 256*j;
            int r = idx >> 3, c4 = idx & 7;
            float4 v = *(const float4*)(Wm + (size_t)(n0 + r)*KTOT + k0 + c4*4);
            uint2 hh, ll; split4(v, hh, ll);
            *reinterpret_cast<uint2*>(&Bs[0][r*STR + c4*2]) = hh;
            *reinterpret_cast<uint2*>(&Bs[1][r*STR + c4*2]) = ll;
        }
        __syncthreads();

        #pragma unroll
        for (int ks = 0; ks < 2; ks++) {
            int kw = ks*8 + lc;
            uint32_t af[TM][4];
            // phase 1: A-hi -> hh + hl
            #pragma unroll
            for (int mb = 0; mb < TM; mb++) {
                int r0 = wm*TM*16 + mb*16 + lr;
                af[mb][0] = As[0][r0*STR + kw];
                af[mb][1] = As[0][(r0+8)*STR + kw];
                af[mb][2] = As[0][r0*STR + kw + 4];
                af[mb][3] = As[0][(r0+8)*STR + kw + 4];
            }
            #pragma unroll
            for (int nb = 0; nb < 4; nb++) {
                int n = wn*32 + nb*8 + lr;
                uint32_t bh0 = Bs[0][n*STR + kw], bh1 = Bs[0][n*STR + kw + 4];
                uint32_t bl0 = Bs[1][n*STR + kw], bl1 = Bs[1][n*STR + kw + 4];
                #pragma unroll
                for (int mb = 0; mb < TM; mb++) {
                    mma16816(acc[mb][nb], af[mb], bh0, bh1);
                    mma16816(acc[mb][nb], af[mb], bl0, bl1);
                }
            }
            // phase 2: A-lo -> lh
            #pragma unroll
            for (int mb = 0; mb < TM; mb++) {
                int r0 = wm*TM*16 + mb*16 + lr;
                af[mb][0] = As[1][r0*STR + kw];
                af[mb][1] = As[1][(r0+8)*STR + kw];
                af[mb][2] = As[1][r0*STR + kw + 4];
                af[mb][3] = As[1][(r0+8)*STR + kw + 4];
            }
            #pragma unroll
            for (int nb = 0; nb < 4; nb++) {
                int n = wn*32 + nb*8 + lr;
                uint32_t bh0 = Bs[0][n*STR + kw], bh1 = Bs[0][n*STR + kw + 4];
                #pragma unroll
                for (int mb = 0; mb < TM; mb++)
                    mma16816(acc[mb][nb], af[mb], bh0, bh1);
            }
        }
        __syncthreads();
    }

    // ---- epilogue ----
    #pragma unroll
    for (int mb = 0; mb < TM; mb++) {
        int row = m0 + wm*TM*16 + mb*16 + lr;
        #pragma unroll
        for (int nb = 0; nb < 4; nb++) {
            int col = n0 + wn*32 + nb*8 + lc*2;
            float b0 = bias[col], b1 = bias[col+1];
            float2 o0, o1;
            o0.x = acc[mb][nb][0] + b0; o0.y = acc[mb][nb][1] + b1;
            o1.x = acc[mb][nb][2] + b0; o1.y = acc[mb][nb][3] + b1;
            *(float2*)(C + (size_t)row*Nfull + col) = o0;
            *(float2*)(C + (size_t)(row+8)*Nfull + col) = o1;
        }
    }
}

// ---------------- BN stats (launch with exactly C threads, C<=256) ----------------
__global__ void k_stats1(const float* __restrict__ h, int C, int rpb) {
    int c = blockIdx.y*256 + threadIdx.x;
    if (c >= C) return;
    size_t base = (size_t)blockIdx.x * rpb * C + c;
    float s = 0.f, q = 0.f;
    for (int r = 0; r < rpb; r++) {
        float v = h[base + (size_t)r*C];
        s += v; q += v*v;
    }
    g_psum[blockIdx.x*C + c] = s;
    g_psq [blockIdx.x*C + c] = q;
}

__global__ void k_stats2(const float* __restrict__ gam, const float* __restrict__ bet,
                         int C, int nb, float invM, int slot) {
    int c = blockIdx.x*256 + threadIdx.x;
    if (c >= C) return;
    float s = 0.f, q = 0.f;
    #pragma unroll 4
    for (int i = 0; i < nb; i++) { s += g_psum[i*C + c]; q += g_psq[i*C + c]; }
    float mean = s * invM;
    float var  = q * invM - mean*mean;
    float sc = gam[c] * rsqrtf(var + BN_EPS);
    g_scl[slot*1024 + c] = sc;
    g_sft[slot*1024 + c] = bet[c] - mean*sc;
}

// ---------------- normalize + lrelu + maxpool over k (read-only) ----------------
__global__ void k_pool(const float* __restrict__ h, int C, int off, int slot) {
    int bn = blockIdx.x;
    int c = threadIdx.x;
    float sc = g_scl[slot*1024 + c], sh = g_sft[slot*1024 + c];
    float mx = -FLT_MAX;
    size_t base = (size_t)bn*KNN*C + c;
    #pragma unroll 4
    for (int kk = 0; kk < KNN; kk++) {
        float v = fmaf(h[base + (size_t)kk*C], sc, sh);
        v = (v >= 0.f) ? v : SLOPE*v;
        mx = fmaxf(mx, v);
    }
    g_xc[bn*512 + off + c] = mx;
}

// final normalize: vectorized float4, C=1024
__global__ void k_normout(const float4* __restrict__ h, float4* __restrict__ out, int slot) {
    int i = blockIdx.x*256 + threadIdx.x;   // i indexes float4, total P2*1024/4
    int c = (i & 255) << 2;
    const float* scl = g_scl + slot*1024;
    const float* sft = g_sft + slot*1024;
    float4 v = h[i];
    float4 s4 = *(const float4*)(scl + c);
    float4 t4 = *(const float4*)(sft + c);
    v.x = fmaf(v.x, s4.x, t4.x); v.y = fmaf(v.y, s4.y, t4.y);
    v.z = fmaf(v.z, s4.z, t4.z); v.w = fmaf(v.w, s4.w, t4.w);
    v.x = (v.x >= 0.f) ? v.x : SLOPE*v.x;
    v.y = (v.y >= 0.f) ? v.y : SLOPE*v.y;
    v.z = (v.z >= 0.f) ? v.z : SLOPE*v.z;
    v.w = (v.w >= 0.f) ? v.w : SLOPE*v.w;
    out[i] = v;
}

// ---------------- launch ----------------
extern "C" void kernel_launch(void* const* d_in, const int* in_sizes, int n_in,
                              void* d_out, int out_size) {
    const float* x = (const float*)d_in[0];
    const float* w[7]; const float* bi[7]; const float* ga[7]; const float* be[7];
    for (int i = 1; i <= 6; i++) {
        w [i] = (const float*)d_in[1 + 4*(i-1) + 0];
        bi[i] = (const float*)d_in[1 + 4*(i-1) + 1];
        ga[i] = (const float*)d_in[1 + 4*(i-1) + 2];
        be[i] = (const float*)d_in[1 + 4*(i-1) + 3];
    }
    float* out = (float*)d_out;

    float *w1p, *h1, *h2, *h3, *h4, *xc, *h5, *h6, *scl, *sft;
    cudaGetSymbolAddress((void**)&w1p, g_w1p);
    cudaGetSymbolAddress((void**)&h1,  g_h1);
    cudaGetSymbolAddress((void**)&h2,  g_h2);
    cudaGetSymbolAddress((void**)&h3,  g_h3);
    cudaGetSymbolAddress((void**)&h4,  g_h4);
    cudaGetSymbolAddress((void**)&xc,  g_xc);
    cudaGetSymbolAddress((void**)&h5,  g_h5);
    cudaGetSymbolAddress((void**)&h6,  g_h6);
    cudaGetSymbolAddress((void**)&scl, g_scl);
    cudaGetSymbolAddress((void**)&sft, g_sft);

    const int knn_smem = (1024 + 16 + 16384 + 64*68) * 4;
    cudaFuncSetAttribute(k_knn, cudaFuncAttributeMaxDynamicSharedMemorySize, knn_smem);

    k_transpose<<<dim3(BATCH, 4), 256>>>(x);
    k_knn<<<dim3(NPTS/16, BATCH), 256, knn_smem>>>();
    k_padw1<<<64, 128>>>(w[1]);

    // layer 1: gather(120->128) -> 64
    k_gemm_mma<64,128,2><<<dim3(P1/128, 1), 256>>>(nullptr, w1p, bi[1], nullptr, nullptr, h1, 64);
    k_stats1<<<dim3(320, 1), 64>>>(h1, 64, 512);
    k_stats2<<<1, 64>>>(ga[1], be[1], 64, 320, 1.f/(float)P1, 0);
    k_pool<<<P2, 64>>>(h1, 64, 0, 0);

    // layer 2: 64 -> 64
    k_gemm_mma<64,64,1><<<dim3(P1/128, 1), 256>>>(h1, w[2], bi[2], scl + 0*1024, sft + 0*1024, h2, 64);
    k_stats1<<<dim3(320, 1), 64>>>(h2, 64, 512);
    k_stats2<<<1, 64>>>(ga[2], be[2], 64, 320, 1.f/(float)P1, 1);
    k_pool<<<P2, 64>>>(h2, 64, 64, 1);

    // layer 3: 64 -> 128
    k_gemm_mma<128,64,1><<<dim3(P1/128, 1), 256>>>(h2, w[3], bi[3], scl + 1*1024, sft + 1*1024, h3, 128);
    k_stats1<<<dim3(320, 1), 128>>>(h3, 128, 512);
    k_stats2<<<1, 128>>>(ga[3], be[3], 128, 320, 1.f/(float)P1, 2);
    k_pool<<<P2, 128>>>(h3, 128, 128, 2);

    // layer 4: 128 -> 256
    k_gemm_mma<128,128,1><<<dim3(P1/128, 2), 256>>>(h3, w[4], bi[4], scl + 2*1024, sft + 2*1024, h4, 256);
    k_stats1<<<dim3(320, 1), 256>>>(h4, 256, 512);
    k_stats2<<<1, 256>>>(ga[4], be[4], 256, 320, 1.f/(float)P1, 3);
    k_pool<<<P2, 256>>>(h4, 256, 256, 3);

    // layer 5: 512 -> 256 on xc (already activated)
    k_gemm_mma<128,512,0><<<dim3(P2/128, 2), 256>>>(xc, w[5], bi[5], nullptr, nullptr, h5, 256);
    k_stats1<<<dim3(128, 1), 256>>>(h5, 256, 64);
    k_stats2<<<1, 256>>>(ga[5], be[5], 256, 128, 1.f/(float)P2, 4);

    // layer 6: 256 -> 1024, then normalize to output
    k_gemm_mma<128,256,1><<<dim3(P2/128, 8), 256>>>(h5, w[6], bi[6], scl + 4*1024, sft + 4*1024, h6, 1024);
    k_stats1<<<dim3(128, 4), 256>>>(h6, 1024, 64);
    k_stats2<<<4, 256>>>(ga[6], be[6], 1024, 128, 1.f/(float)P2, 5);
    k_normout<<<(P2*1024/4)/256, 256>>>((const float4*)h6, (float4*)out, 5);
}

// round 16
// speedup vs baseline: 1.5641x; 1.5641x over previous
#include <cuda_runtime.h>
#include <cuda_bf16.h>
#include <cfloat>
#include <cstdint>

#define NPTS 1024
#define BATCH 8
#define DIN 60
#define DPAD 64
#define KNN 20
#define P1 (BATCH*NPTS*KNN)   /* 163840 */
#define P2 (BATCH*NPTS)       /* 8192 */
#define BN_EPS 1e-5f
#define SLOPE 0.2f

// ---------------- scratch ----------------
__device__ float g_xt[BATCH*NPTS*DPAD];
__device__ float g_xx[BATCH*NPTS];
__device__ int   g_idx[BATCH*NPTS*KNN];
__device__ float g_w1p[64*128];
__device__ float g_h1[P1*64];
__device__ float g_h2[P1*64];
__device__ float g_h3[P1*128];
__device__ float g_h4[P1*256];
__device__ float g_xc[P2*512];
__device__ float g_h5[P2*256];
__device__ float g_h6[P2*1024];
__device__ float g_psum[640*1024];
__device__ float g_psq[640*1024];
__device__ float g_scl[6*1024];
__device__ float g_sft[6*1024];

// ---------------- transpose + squared norm ----------------
__global__ void k_transpose(const float* __restrict__ x) {
    int b = blockIdx.x;
    int n = blockIdx.y * 256 + threadIdx.x;
    float ss = 0.f;
    int obase = (b*NPTS + n)*DPAD;
    #pragma unroll 4
    for (int d = 0; d < DIN; d++) {
        float v = x[(b*DIN + d)*NPTS + n];
        g_xt[obase + d] = v;
        ss += v*v;
    }
    #pragma unroll
    for (int d = DIN; d < DPAD; d++) g_xt[obase + d] = 0.f;
    g_xx[b*NPTS + n] = ss;
}

// ---------------- knn (validated) ----------------
extern __shared__ float s_knn[];
__global__ __launch_bounds__(256) void k_knn() {
    int bb = blockIdx.y;
    int q0 = blockIdx.x * 16;
    float* qs  = s_knn;
    float* xxq = s_knn + 1024;
    float* pd  = s_knn + 1040;
    float* cs  = s_knn + 1040 + 16384;
    int tid = threadIdx.x;
    {
        const float4* src = (const float4*)(g_xt + (bb*NPTS + q0)*DPAD);
        ((float4*)qs)[tid] = src[tid];
    }
    if (tid < 16) xxq[tid] = g_xx[bb*NPTS + q0 + tid];
    __syncthreads();
    int qi0 = (tid >> 5) << 1;
    int mi0 = (tid & 31) << 1;
    for (int t = 0; t < NPTS/64; t++) {
        int m0 = t*64;
        {
            const float4* src = (const float4*)(g_xt + (bb*NPTS + m0)*DPAD);
            #pragma unroll
            for (int j = 0; j < 4; j++) {
                int i = tid + 256*j;
                int row = i >> 4, col = i & 15;
                float4 v = src[row*16 + col];
                float* dr = cs + row*68 + col*4;
                dr[0]=v.x; dr[1]=v.y; dr[2]=v.z; dr[3]=v.w;
            }
        }
        __syncthreads();
        float a00=0,a01=0,a10=0,a11=0;
        #pragma unroll
        for (int d4 = 0; d4 < 16; d4++) {
            float4 qa = *(const float4*)(qs + qi0*64 + d4*4);
            float4 qb = *(const float4*)(qs + (qi0+1)*64 + d4*4);
            float4 ca = *(const float4*)(cs + mi0*68 + d4*4);
            float4 cb = *(const float4*)(cs + (mi0+1)*68 + d4*4);
            a00 += qa.x*ca.x + qa.y*ca.y + qa.z*ca.z + qa.w*ca.w;
            a01 += qa.x*cb.x + qa.y*cb.y + qa.z*cb.z + qa.w*cb.w;
            a10 += qb.x*ca.x + qb.y*ca.y + qb.z*ca.z + qb.w*ca.w;
            a11 += qb.x*cb.x + qb.y*cb.y + qb.z*cb.z + qb.w*cb.w;
        }
        float xc0 = g_xx[bb*NPTS + m0 + mi0];
        float xc1 = g_xx[bb*NPTS + m0 + mi0 + 1];
        pd[(qi0  )*NPTS + m0 + mi0    ] = 2.f*a00 - xxq[qi0  ] - xc0;
        pd[(qi0  )*NPTS + m0 + mi0 + 1] = 2.f*a01 - xxq[qi0  ] - xc1;
        pd[(qi0+1)*NPTS + m0 + mi0    ] = 2.f*a10 - xxq[qi0+1] - xc0;
        pd[(qi0+1)*NPTS + m0 + mi0 + 1] = 2.f*a11 - xxq[qi0+1] - xc1;
        __syncthreads();
    }
    int w = tid >> 5, lane = tid & 31;
    for (int t = 0; t < 2; t++) {
        int qi = w*2 + t;
        float* row = pd + qi*NPTS;
        for (int it = 0; it < KNN; it++) {
            float best = -FLT_MAX; int bi = NPTS;
            for (int m = lane; m < NPTS; m += 32) {
                float v = row[m];
                if (v > best) { best = v; bi = m; }
            }
            #pragma unroll
            for (int off = 16; off; off >>= 1) {
                float ov = __shfl_down_sync(0xffffffffu, best, off);
                int   oi = __shfl_down_sync(0xffffffffu, bi,   off);
                if (ov > best || (ov == best && oi < bi)) { best = ov; bi = oi; }
            }
            bi = __shfl_sync(0xffffffffu, bi, 0);
            if (lane == 0) {
                g_idx[(bb*NPTS + q0 + qi)*KNN + it] = bi;
                row[bi] = -FLT_MAX;
            }
            __syncwarp();
        }
    }
}

__global__ void k_padw1(const float* __restrict__ w1) {
    int o = blockIdx.x, c = threadIdx.x;
    g_w1p[o*128 + c] = (c < 120) ? w1[o*120 + c] : 0.f;
}

// ---------------- helpers ----------------
__device__ __forceinline__ void split4(float4 v, uint2& hh, uint2& ll) {
    __nv_bfloat162 ph0 = __floats2bfloat162_rn(v.x, v.y);
    __nv_bfloat162 ph1 = __floats2bfloat162_rn(v.z, v.w);
    __nv_bfloat162 pl0 = __floats2bfloat162_rn(v.x - __low2float(ph0), v.y - __high2float(ph0));
    __nv_bfloat162 pl1 = __floats2bfloat162_rn(v.z - __low2float(ph1), v.w - __high2float(ph1));
    hh.x = *reinterpret_cast<uint32_t*>(&ph0); hh.y = *reinterpret_cast<uint32_t*>(&ph1);
    ll.x = *reinterpret_cast<uint32_t*>(&pl0); ll.y = *reinterpret_cast<uint32_t*>(&pl1);
}

__device__ __forceinline__ void mma16816(float* d, const uint32_t* a, uint32_t b0, uint32_t b1) {
    asm volatile("mma.sync.aligned.m16n8k16.row.col.f32.bf16.bf16.f32 "
                 "{%0,%1,%2,%3}, {%4,%5,%6,%7}, {%8,%9}, {%0,%1,%2,%3};"
                 : "+f"(d[0]), "+f"(d[1]), "+f"(d[2]), "+f"(d[3])
                 : "r"(a[0]), "r"(a[1]), "r"(a[2]), "r"(a[3]), "r"(b0), "r"(b1));
}

__device__ __forceinline__ void ldsm4(uint32_t* r, uint32_t addr) {
    asm volatile("ldmatrix.sync.aligned.m8n8.x4.shared.b16 {%0,%1,%2,%3}, [%4];"
                 : "=r"(r[0]), "=r"(r[1]), "=r"(r[2]), "=r"(r[3]) : "r"(addr));
}

// ---------------- mma.sync bf16-split GEMM, ldmatrix + reg-prefetch pipeline ----------------
// C[M, n0..n0+NT] = A[M,K] * W[N,K]^T + bias, fp32 accum.
// MODE 0: plain A. MODE 1: A = lrelu(A*scl+sft). MODE 2: graph-feature gather.
template<int NT, int KTOT, int MODE>
__global__ __launch_bounds__(256, 2)
void k_gemm_mma(const float* __restrict__ Ain, const float* __restrict__ Wm,
                const float* __restrict__ bias, const float* __restrict__ scl,
                const float* __restrict__ sft, float* __restrict__ C, int Nfull)
{
    constexpr int WN = NT/32;          // warps along n (2 or 4)
    constexpr int WM = 8/WN;           // warps along m (4 or 2)
    constexpr int TM = 128/(WM*16);    // m16 blocks per warp (2 or 4)
    constexpr int STR = 20;            // uint32 words per smem row (80B, ldmatrix conflict-free)
    constexpr int BJ = NT/32;          // B float4 loads per thread
    __shared__ __align__(16) uint32_t As[2][128*STR];   // 16B align: ldmatrix requirement
    __shared__ __align__(16) uint32_t Bs[2][NT*STR];

    int tid = threadIdx.x;
    int warp = tid >> 5, lane = tid & 31;
    int wm = warp % WM, wn = warp / WM;
    int m0 = blockIdx.x * 128;
    int n0 = blockIdx.y * NT;
    int lr = lane >> 2, lc = lane & 3;

    // ldmatrix per-lane address components (byte offsets within hi/lo planes)
    int t8 = lane >> 3, l8 = lane & 7;
    uint32_t aoff = (uint32_t)((wm*TM*16 + (t8 & 1)*8 + l8)*80 + (t8 >> 1)*16);
    uint32_t boff0 = (uint32_t)((wn*32 + (t8 >> 1)*8 + l8)*80 + (t8 & 1)*16);
    uint32_t boff1 = boff0 + 16*80;
    uint32_t baseAh = (uint32_t)__cvta_generic_to_shared(&As[0][0]);
    uint32_t baseAl = (uint32_t)__cvta_generic_to_shared(&As[1][0]);
    uint32_t baseBh = (uint32_t)__cvta_generic_to_shared(&Bs[0][0]);
    uint32_t baseBl = (uint32_t)__cvta_generic_to_shared(&Bs[1][0]);

    float acc[TM][4][4];
    #pragma unroll
    for (int i = 0; i < TM; i++)
        #pragma unroll
        for (int j = 0; j < 4; j++)
            #pragma unroll
            for (int q = 0; q < 4; q++) acc[i][j][q] = 0.f;

    float4 aR[4];
    float4 bR[BJ];

    // ---- global loaders (into registers) ----
    auto loadA = [&](int k0) {
        #pragma unroll
        for (int j = 0; j < 4; j++) {
            int idx = tid + 256*j;
            int r = idx >> 3, c4 = idx & 7;
            int kk = k0 + c4*4;
            if (MODE == 2) {
                int p = m0 + r;
                int bn = p / KNN;
                int b = bn >> 10;
                int nb = g_idx[p];
                int cbase = bn * DPAD;
                int nbase = ((b << 10) + nb) * DPAD;
                float e[4];
                #pragma unroll
                for (int q = 0; q < 4; q++) {
                    int k = kk + q;
                    float val;
                    if (k < 60)       val = g_xt[nbase + k] - g_xt[cbase + k];
                    else if (k < 120) val = g_xt[cbase + k - 60];
                    else              val = 0.f;
                    e[q] = val;
                }
                aR[j].x = e[0]; aR[j].y = e[1]; aR[j].z = e[2]; aR[j].w = e[3];
            } else {
                float4 v = *(const float4*)(Ain + (size_t)(m0 + r)*KTOT + kk);
                if (MODE == 1) {
                    float4 s4 = *(const float4*)(scl + kk);
                    float4 t4 = *(const float4*)(sft + kk);
                    v.x = fmaf(v.x, s4.x, t4.x); v.y = fmaf(v.y, s4.y, t4.y);
                    v.z = fmaf(v.z, s4.z, t4.z); v.w = fmaf(v.w, s4.w, t4.w);
                    v.x = (v.x >= 0.f) ? v.x : SLOPE*v.x;
                    v.y = (v.y >= 0.f) ? v.y : SLOPE*v.y;
                    v.z = (v.z >= 0.f) ? v.z : SLOPE*v.z;
                    v.w = (v.w >= 0.f) ? v.w : SLOPE*v.w;
                }
                aR[j] = v;
            }
        }
    };
    auto loadB = [&](int k0) {
        #pragma unroll
        for (int j = 0; j < BJ; j++) {
            int idx = tid + 256*j;
            int r = idx >> 3, c4 = idx & 7;
            bR[j] = *(const float4*)(Wm + (size_t)(n0 + r)*KTOT + k0 + c4*4);
        }
    };
    auto storeAB = [&]() {
        #pragma unroll
        for (int j = 0; j < 4; j++) {
            int idx = tid + 256*j;
            int r = idx >> 3, c4 = idx & 7;
            uint2 hh, ll; split4(aR[j], hh, ll);
            *reinterpret_cast<uint2*>(&As[0][r*STR + c4*2]) = hh;
            *reinterpret_cast<uint2*>(&As[1][r*STR + c4*2]) = ll;
        }
        #pragma unroll
        for (int j = 0; j < BJ; j++) {
            int idx = tid + 256*j;
            int r = idx >> 3, c4 = idx & 7;
            uint2 hh, ll; split4(bR[j], hh, ll);
            *reinterpret_cast<uint2*>(&Bs[0][r*STR + c4*2]) = hh;
            *reinterpret_cast<uint2*>(&Bs[1][r*STR + c4*2]) = ll;
        }
    };

    loadA(0); loadB(0);

    for (int k0 = 0; k0 < KTOT; k0 += 32) {
        storeAB();
        __syncthreads();
        if (k0 + 32 < KTOT) { loadA(k0 + 32); loadB(k0 + 32); }  // overlap with compute

        #pragma unroll
        for (int ks = 0; ks < 2; ks++) {
            uint32_t kadd = ks*32;
            uint32_t bh[4][2], bl[4][2], q[4];
            ldsm4(q, baseBh + boff0 + kadd);
            bh[0][0]=q[0]; bh[0][1]=q[1]; bh[1][0]=q[2]; bh[1][1]=q[3];
            ldsm4(q, baseBh + boff1 + kadd);
            bh[2][0]=q[0]; bh[2][1]=q[1]; bh[3][0]=q[2]; bh[3][1]=q[3];
            ldsm4(q, baseBl + boff0 + kadd);
            bl[0][0]=q[0]; bl[0][1]=q[1]; bl[1][0]=q[2]; bl[1][1]=q[3];
            ldsm4(q, baseBl + boff1 + kadd);
            bl[2][0]=q[0]; bl[2][1]=q[1]; bl[3][0]=q[2]; bl[3][1]=q[3];
            // per-mb fragment loads keep register peak under the 2-CTA cap (TM=4 case)
            #pragma unroll
            for (int mb = 0; mb < TM; mb++) {
                uint32_t ah[4], al[4];
                ldsm4(ah, baseAh + aoff + mb*1280 + kadd);
                ldsm4(al, baseAl + aoff + mb*1280 + kadd);
                #pragma unroll
                for (int nb = 0; nb < 4; nb++) {
                    mma16816(acc[mb][nb], ah, bh[nb][0], bh[nb][1]);
                    mma16816(acc[mb][nb], ah, bl[nb][0], bl[nb][1]);
                    mma16816(acc[mb][nb], al, bh[nb][0], bh[nb][1]);
                }
            }
        }
        __syncthreads();
    }

    // ---- epilogue ----
    #pragma unroll
    for (int mb = 0; mb < TM; mb++) {
        int row = m0 + wm*TM*16 + mb*16 + lr;
        #pragma unroll
        for (int nb = 0; nb < 4; nb++) {
            int col = n0 + wn*32 + nb*8 + lc*2;
            float b0 = bias[col], b1 = bias[col+1];
            float2 o0, o1;
            o0.x = acc[mb][nb][0] + b0; o0.y = acc[mb][nb][1] + b1;
            o1.x = acc[mb][nb][2] + b0; o1.y = acc[mb][nb][3] + b1;
            *(float2*)(C + (size_t)row*Nfull + col) = o0;
            *(float2*)(C + (size_t)(row+8)*Nfull + col) = o1;
        }
    }
}

// ---------------- BN stats ----------------
__global__ void k_stats1(const float* __restrict__ h, int C, int rpb) {
    int c = blockIdx.y*256 + threadIdx.x;
    if (c >= C) return;
    size_t base = (size_t)blockIdx.x * rpb * C + c;
    float s = 0.f, q = 0.f;
    for (int r = 0; r < rpb; r++) {
        float v = h[base + (size_t)r*C];
        s += v; q += v*v;
    }
    g_psum[blockIdx.x*C + c] = s;
    g_psq [blockIdx.x*C + c] = q;
}

__global__ void k_stats2(const float* __restrict__ gam, const float* __restrict__ bet,
                         int C, int nb, float invM, int slot) {
    int c = blockIdx.x*256 + threadIdx.x;
    if (c >= C) return;
    float s = 0.f, q = 0.f;
    #pragma unroll 4
    for (int i = 0; i < nb; i++) { s += g_psum[i*C + c]; q += g_psq[i*C + c]; }
    float mean = s * invM;
    float var  = q * invM - mean*mean;
    float sc = gam[c] * rsqrtf(var + BN_EPS);
    g_scl[slot*1024 + c] = sc;
    g_sft[slot*1024 + c] = bet[c] - mean*sc;
}

// ---------------- normalize + lrelu + maxpool over k (read-only) ----------------
__global__ void k_pool(const float* __restrict__ h, int C, int off, int slot) {
    int bn = blockIdx.x;
    int c = threadIdx.x;
    float sc = g_scl[slot*1024 + c], sh = g_sft[slot*1024 + c];
    float mx = -FLT_MAX;
    size_t base = (size_t)bn*KNN*C + c;
    #pragma unroll 4
    for (int kk = 0; kk < KNN; kk++) {
        float v = fmaf(h[base + (size_t)kk*C], sc, sh);
        v = (v >= 0.f) ? v : SLOPE*v;
        mx = fmaxf(mx, v);
    }
    g_xc[bn*512 + off + c] = mx;
}

// final normalize: vectorized float4, C=1024
__global__ void k_normout(const float4* __restrict__ h, float4* __restrict__ out, int slot) {
    int i = blockIdx.x*256 + threadIdx.x;
    int c = (i & 255) << 2;
    const float* scl = g_scl + slot*1024;
    const float* sft = g_sft + slot*1024;
    float4 v = h[i];
    float4 s4 = *(const float4*)(scl + c);
    float4 t4 = *(const float4*)(sft + c);
    v.x = fmaf(v.x, s4.x, t4.x); v.y = fmaf(v.y, s4.y, t4.y);
    v.z = fmaf(v.z, s4.z, t4.z); v.w = fmaf(v.w, s4.w, t4.w);
    v.x = (v.x >= 0.f) ? v.x : SLOPE*v.x;
    v.y = (v.y >= 0.f) ? v.y : SLOPE*v.y;
    v.z = (v.z >= 0.f) ? v.z : SLOPE*v.z;
    v.w = (v.w >= 0.f) ? v.w : SLOPE*v.w;
    out[i] = v;
}

// ---------------- launch ----------------
extern "C" void kernel_launch(void* const* d_in, const int* in_sizes, int n_in,
                              void* d_out, int out_size) {
    const float* x = (const float*)d_in[0];
    const float* w[7]; const float* bi[7]; const float* ga[7]; const float* be[7];
    for (int i = 1; i <= 6; i++) {
        w [i] = (const float*)d_in[1 + 4*(i-1) + 0];
        bi[i] = (const float*)d_in[1 + 4*(i-1) + 1];
        ga[i] = (const float*)d_in[1 + 4*(i-1) + 2];
        be[i] = (const float*)d_in[1 + 4*(i-1) + 3];
    }
    float* out = (float*)d_out;

    float *w1p, *h1, *h2, *h3, *h4, *xc, *h5, *h6, *scl, *sft;
    cudaGetSymbolAddress((void**)&w1p, g_w1p);
    cudaGetSymbolAddress((void**)&h1,  g_h1);
    cudaGetSymbolAddress((void**)&h2,  g_h2);
    cudaGetSymbolAddress((void**)&h3,  g_h3);
    cudaGetSymbolAddress((void**)&h4,  g_h4);
    cudaGetSymbolAddress((void**)&xc,  g_xc);
    cudaGetSymbolAddress((void**)&h5,  g_h5);
    cudaGetSymbolAddress((void**)&h6,  g_h6);
    cudaGetSymbolAddress((void**)&scl, g_scl);
    cudaGetSymbolAddress((void**)&sft, g_sft);

    const int knn_smem = (1024 + 16 + 16384 + 64*68) * 4;
    cudaFuncSetAttribute(k_knn, cudaFuncAttributeMaxDynamicSharedMemorySize, knn_smem);

    k_transpose<<<dim3(BATCH, 4), 256>>>(x);
    k_knn<<<dim3(NPTS/16, BATCH), 256, knn_smem>>>();
    k_padw1<<<64, 128>>>(w[1]);

    // layer 1: gather(120->128) -> 64
    k_gemm_mma<64,128,2><<<dim3(P1/128, 1), 256>>>(nullptr, w1p, bi[1], nullptr, nullptr, h1, 64);
    k_stats1<<<dim3(320, 1), 64>>>(h1, 64, 512);
    k_stats2<<<1, 64>>>(ga[1], be[1], 64, 320, 1.f/(float)P1, 0);
    k_pool<<<P2, 64>>>(h1, 64, 0, 0);

    // layer 2: 64 -> 64
    k_gemm_mma<64,64,1><<<dim3(P1/128, 1), 256>>>(h1, w[2], bi[2], scl + 0*1024, sft + 0*1024, h2, 64);
    k_stats1<<<dim3(320, 1), 64>>>(h2, 64, 512);
    k_stats2<<<1, 64>>>(ga[2], be[2], 64, 320, 1.f/(float)P1, 1);
    k_pool<<<P2, 64>>>(h2, 64, 64, 1);

    // layer 3: 64 -> 128
    k_gemm_mma<128,64,1><<<dim3(P1/128, 1), 256>>>(h2, w[3], bi[3], scl + 1*1024, sft + 1*1024, h3, 128);
    k_stats1<<<dim3(320, 1), 128>>>(h3, 128, 512);
    k_stats2<<<1, 128>>>(ga[3], be[3], 128, 320, 1.f/(float)P1, 2);
    k_pool<<<P2, 128>>>(h3, 128, 128, 2);

    // layer 4: 128 -> 256
    k_gemm_mma<128,128,1><<<dim3(P1/128, 2), 256>>>(h3, w[4], bi[4], scl + 2*1024, sft + 2*1024, h4, 256);
    k_stats1<<<dim3(320, 1), 256>>>(h4, 256, 512);
    k_stats2<<<1, 256>>>(ga[4], be[4], 256, 320, 1.f/(float)P1, 3);
    k_pool<<<P2, 256>>>(h4, 256, 256, 3);

    // layer 5: 512 -> 256 on xc (already activated)
    k_gemm_mma<128,512,0><<<dim3(P2/128, 2), 256>>>(xc, w[5], bi[5], nullptr, nullptr, h5, 256);
    k_stats1<<<dim3(128, 1), 256>>>(h5, 256, 64);
    k_stats2<<<1, 256>>>(ga[5], be[5], 256, 128, 1.f/(float)P2, 4);

    // layer 6: 256 -> 1024, then normalize to output
    k_gemm_mma<128,256,1><<<dim3(P2/128, 8), 256>>>(h5, w[6], bi[6], scl + 4*1024, sft + 4*1024, h6, 1024);
    k_stats1<<<dim3(128, 4), 256>>>(h6, 1024, 64);
    k_stats2<<<4, 256>>>(ga[6], be[6], 1024, 128, 1.f/(float)P2, 5);
    k_normout<<<(P2*1024/4)/256, 256>>>((const float4*)h6, (float4*)out, 5);
}